// round 10
// baseline (speedup 1.0000x reference)
#include <cuda_runtime.h>
#include <cuda_fp16.h>

#define NMAX   100000
#define EMAX   3200000
#define FIN    128
#define FH     64
#define FC     16
#define SCANB  1024
#define NBLK   ((NMAX + SCANB - 1) / SCANB)   // 98

// ---- scratch (allocation-free: __device__ globals) ----
__device__ __align__(16) __half g_h1h[NMAX * FH];   // layer-1 h' = (x@W1)*dinv, fp16
__device__ __align__(16) __half g_h2h[NMAX * FC];   // layer-2 h' = (z@W2)*dinv, fp16
__device__ int   g_deg[NMAX];
__device__ float g_dinv[NMAX];
__device__ int   g_rowstart[NMAX + 1];
__device__ int   g_cursor[NMAX];
__device__ int   g_adj[EMAX];                        // CSR by dst: stores src ids
__device__ int   g_bsum[NBLK];
__device__ int   g_boff[NBLK];

// ---------------------------------------------------------------------------
// f32x2 packed-FMA helpers (sm_100+; ptxas won't auto-fuse from C++)
__device__ __forceinline__ unsigned long long pack2(float a, float b) {
    unsigned long long r;
    asm("mov.b64 %0, {%1, %2};" : "=l"(r) : "f"(a), "f"(b));
    return r;
}
__device__ __forceinline__ void unpack2(unsigned long long v, float& a, float& b) {
    asm("mov.b64 {%0, %1}, %2;" : "=f"(a), "=f"(b) : "l"(v));
}
__device__ __forceinline__ void fma2(unsigned long long& d,
                                     unsigned long long a, unsigned long long b) {
    asm("fma.rn.f32x2 %0, %1, %2, %0;" : "+l"(d) : "l"(a), "l"(b));
}

// ---------------------------------------------------------------------------
__global__ void k_zero_deg(int n) {
    int i = blockIdx.x * blockDim.x + threadIdx.x;
    if (i < n) g_deg[i] = 0;
}

__global__ void k_degree(const int* __restrict__ dst, int e) {
    int i = blockIdx.x * blockDim.x + threadIdx.x;
    if (i < e) atomicAdd(&g_deg[dst[i]], 1);
}

// ---- prefix scan (exclusive) of g_deg -> g_rowstart + dinv fused ----
__global__ void k_scan1(int n) {
    __shared__ int s[SCANB];
    int i = blockIdx.x * SCANB + threadIdx.x;
    int v = (i < n) ? g_deg[i] : 0;
    if (i < n) g_dinv[i] = rsqrtf((float)v + 1.0f);
    s[threadIdx.x] = v;
    __syncthreads();
    for (int off = 1; off < SCANB; off <<= 1) {
        int t = (threadIdx.x >= off) ? s[threadIdx.x - off] : 0;
        __syncthreads();
        s[threadIdx.x] += t;
        __syncthreads();
    }
    if (i < n) g_rowstart[i] = s[threadIdx.x] - v;   // exclusive, block-local
    if (threadIdx.x == SCANB - 1) g_bsum[blockIdx.x] = s[SCANB - 1];
}

// parallel scan of block sums (one 128-thread block)
__global__ void k_scan2(int nb) {
    __shared__ int s[128];
    int tid = threadIdx.x;
    int v = (tid < nb) ? g_bsum[tid] : 0;
    s[tid] = v;
    __syncthreads();
    for (int off = 1; off < 128; off <<= 1) {
        int t = (tid >= off) ? s[tid - off] : 0;
        __syncthreads();
        s[tid] += t;
        __syncthreads();
    }
    if (tid < nb) g_boff[tid] = s[tid] - v;   // exclusive
}

__global__ void k_scan3(int n, int e) {
    int i = blockIdx.x * blockDim.x + threadIdx.x;
    if (i < n) {
        int r = g_rowstart[i] + g_boff[i / SCANB];
        g_rowstart[i] = r;
        g_cursor[i]   = r;
    }
    if (i == 0) g_rowstart[n] = e;
}

__global__ void k_fill(const int* __restrict__ src, const int* __restrict__ dst, int e) {
    int i = blockIdx.x * blockDim.x + threadIdx.x;
    if (i >= e) return;
    int pos = atomicAdd(&g_cursor[dst[i]], 1);
    g_adj[pos] = src[i];
}

// ---------------------------------------------------------------------------
// Layer-1 GEMM: h1[row] = (x[row] @ W1) * dinv[row], stored fp16.
// Register tile: 4 rows x 16 cols per thread, f32x2 packed FMA.
__global__ void __launch_bounds__(256) k_gemm1(const float* __restrict__ x,
                                               const float* __restrict__ W1, int n) {
    __shared__ float Ws[FIN * FH];   // 32 KB, [k][j]
    for (int i = threadIdx.x; i < (FIN * FH) / 4; i += blockDim.x)
        reinterpret_cast<float4*>(Ws)[i] = reinterpret_cast<const float4*>(W1)[i];
    __syncthreads();

    int c16  = threadIdx.x & 3;                 // which 16-col group
    int quad = threadIdx.x >> 2;                // 0..63
    int row0 = blockIdx.x * 256 + quad * 4;

    unsigned long long acc[4][8];
#pragma unroll
    for (int r = 0; r < 4; r++)
#pragma unroll
        for (int p = 0; p < 8; p++) acc[r][p] = 0ull;

    for (int k4 = 0; k4 < FIN / 4; k4++) {
        float4 xv[4];
#pragma unroll
        for (int r = 0; r < 4; r++) {
            int row = row0 + r;
            xv[r] = (row < n)
                ? reinterpret_cast<const float4*>(x + (size_t)row * FIN)[k4]
                : make_float4(0.f, 0.f, 0.f, 0.f);
        }
#pragma unroll
        for (int kk = 0; kk < 4; kk++) {
            int k = k4 * 4 + kk;
            const unsigned long long* wp =
                reinterpret_cast<const unsigned long long*>(Ws + k * FH + c16 * 16);
            unsigned long long w[8];
#pragma unroll
            for (int p = 0; p < 8; p++) w[p] = wp[p];
#pragma unroll
            for (int r = 0; r < 4; r++) {
                float xk = (kk == 0) ? xv[r].x : (kk == 1) ? xv[r].y
                         : (kk == 2) ? xv[r].z : xv[r].w;
                unsigned long long xk2 = pack2(xk, xk);
#pragma unroll
                for (int p = 0; p < 8; p++) fma2(acc[r][p], xk2, w[p]);
            }
        }
    }

#pragma unroll
    for (int r = 0; r < 4; r++) {
        int row = row0 + r;
        if (row >= n) continue;
        float dv = g_dinv[row];
        __align__(16) __half2 hv[8];
#pragma unroll
        for (int p = 0; p < 8; p++) {
            float a, b;
            unpack2(acc[r][p], a, b);
            hv[p] = __floats2half2_rn(a * dv, b * dv);
        }
        const uint4* wsrc = reinterpret_cast<const uint4*>(hv);
        uint4* o = reinterpret_cast<uint4*>(g_h1h + (size_t)row * FH + c16 * 16);
        o[0] = wsrc[0];
        o[1] = wsrc[1];
    }
}

// ---------------------------------------------------------------------------
// Fused gather1 + layer-2 GEMM:
//   8 lanes per node gather 64-dim agg (fp32), z = relu(dv*agg + b1),
//   partial h2 = z_slice @ W2_slice (16 wide), shfl-reduce over the 8-lane
//   group, write h2 = dv * sum  as fp16.
__global__ void __launch_bounds__(256) k_gather1l2(const float* __restrict__ W2,
                                                   const float* __restrict__ b1, int n) {
    __shared__ float Ws[FH * FC];    // 4 KB [k][c]
    __shared__ float b1s[FH];
    for (int i = threadIdx.x; i < (FH * FC) / 4; i += blockDim.x)
        reinterpret_cast<float4*>(Ws)[i] = reinterpret_cast<const float4*>(W2)[i];
    if (threadIdx.x < FH) b1s[threadIdx.x] = b1[threadIdx.x];
    __syncthreads();

    long long t = (long long)blockIdx.x * blockDim.x + threadIdx.x;
    int j = (int)(t & 7);
    int d = (int)(t >> 3);
    bool valid = (d < n);
    if (d >= n) d = n - 1;           // clamp: keep all lanes active for shfl

    int rs = g_rowstart[d];
    int re = g_rowstart[d + 1];

    float acc[8];
    {   // self term
        __align__(16) uint4 v = reinterpret_cast<const uint4*>(g_h1h + (size_t)d * FH + j * 8)[0];
        const __half2* h2p = reinterpret_cast<const __half2*>(&v);
#pragma unroll
        for (int q = 0; q < 4; q++) {
            float2 f = __half22float2(h2p[q]);
            acc[q * 2] = f.x; acc[q * 2 + 1] = f.y;
        }
    }
    for (int e = rs; e < re; e++) {
        int s = g_adj[e];
        __align__(16) uint4 v = reinterpret_cast<const uint4*>(g_h1h + (size_t)s * FH + j * 8)[0];
        const __half2* h2p = reinterpret_cast<const __half2*>(&v);
#pragma unroll
        for (int q = 0; q < 4; q++) {
            float2 f = __half22float2(h2p[q]);
            acc[q * 2] += f.x; acc[q * 2 + 1] += f.y;
        }
    }

    float dv = g_dinv[d];

    // partial h2 (16 wide) from this lane's 8 k's
    unsigned long long part[8];
#pragma unroll
    for (int p = 0; p < 8; p++) part[p] = 0ull;
#pragma unroll
    for (int kk = 0; kk < 8; kk++) {
        int k = j * 8 + kk;
        float z = fmaxf(fmaf(dv, acc[kk], b1s[k]), 0.0f);
        unsigned long long z2 = pack2(z, z);
        const unsigned long long* wp =
            reinterpret_cast<const unsigned long long*>(Ws + k * FC);
#pragma unroll
        for (int p = 0; p < 8; p++) fma2(part[p], z2, wp[p]);
    }

    // reduce across the 8-lane group (width 8)
    float pf[16];
#pragma unroll
    for (int p = 0; p < 8; p++) unpack2(part[p], pf[p * 2], pf[p * 2 + 1]);
#pragma unroll
    for (int off = 4; off >= 1; off >>= 1) {
#pragma unroll
        for (int c = 0; c < 16; c++)
            pf[c] += __shfl_xor_sync(0xffffffffu, pf[c], off, 8);
    }

    // lanes 0 and 1 of each group write 8 halves each (16B)
    if (valid && j < 2) {
        __align__(16) __half2 hv[4];
#pragma unroll
        for (int q = 0; q < 4; q++)
            hv[q] = __floats2half2_rn(pf[j * 8 + q * 2] * dv, pf[j * 8 + q * 2 + 1] * dv);
        reinterpret_cast<uint4*>(g_h2h + (size_t)d * FC + j * 8)[0] =
            reinterpret_cast<const uint4*>(hv)[0];
    }
}

// ---------------------------------------------------------------------------
// gather2 (+ fused final): 4 threads per dst, fp16 h2;
//   out = dinv[d]*(h2[d] + sum h2[src]) + b2
__global__ void k_gather2(float* __restrict__ out, const float* __restrict__ b2, int n) {
    long long t = (long long)blockIdx.x * blockDim.x + threadIdx.x;
    int j = (int)(t & 3);
    int d = (int)(t >> 2);
    if (d >= n) return;

    int rs = g_rowstart[d];
    int re = g_rowstart[d + 1];

    float acc[4];
    {
        __align__(8) uint2 v = reinterpret_cast<const uint2*>(g_h2h + (size_t)d * FC + j * 4)[0];
        const __half2* h2p = reinterpret_cast<const __half2*>(&v);
        float2 f0 = __half22float2(h2p[0]);
        float2 f1 = __half22float2(h2p[1]);
        acc[0] = f0.x; acc[1] = f0.y; acc[2] = f1.x; acc[3] = f1.y;
    }
    for (int e = rs; e < re; e++) {
        int s = g_adj[e];
        __align__(8) uint2 v = reinterpret_cast<const uint2*>(g_h2h + (size_t)s * FC + j * 4)[0];
        const __half2* h2p = reinterpret_cast<const __half2*>(&v);
        float2 f0 = __half22float2(h2p[0]);
        float2 f1 = __half22float2(h2p[1]);
        acc[0] += f0.x; acc[1] += f0.y; acc[2] += f1.x; acc[3] += f1.y;
    }

    float dv = g_dinv[d];
    float4 bb = reinterpret_cast<const float4*>(b2)[j];
    float4 o;
    o.x = fmaf(dv, acc[0], bb.x);
    o.y = fmaf(dv, acc[1], bb.y);
    o.z = fmaf(dv, acc[2], bb.z);
    o.w = fmaf(dv, acc[3], bb.w);
    reinterpret_cast<float4*>(out + (size_t)d * FC + j * 4)[0] = o;
}

// ---------------------------------------------------------------------------
extern "C" void kernel_launch(void* const* d_in, const int* in_sizes, int n_in,
                              void* d_out, int out_size) {
    const float* x  = (const float*)d_in[0];
    const int*   ei = (const int*)d_in[1];   // int32 (JAX x64 disabled)
    const float* W1 = (const float*)d_in[2];
    const float* b1 = (const float*)d_in[3];
    const float* W2 = (const float*)d_in[4];
    const float* b2 = (const float*)d_in[5];
    float* out = (float*)d_out;

    int N = in_sizes[0] / FIN;
    int E = in_sizes[1] / 2;
    const int* src = ei;
    const int* dst = ei + E;
    int nb = (N + SCANB - 1) / SCANB;

    k_zero_deg<<<(N + 255) / 256, 256>>>(N);
    k_degree  <<<(E + 255) / 256, 256>>>(dst, E);

    k_scan1   <<<nb, SCANB>>>(N);
    k_scan2   <<<1, 128>>>(nb);
    k_scan3   <<<(N + 255) / 256, 256>>>(N, E);
    k_fill    <<<(E + 255) / 256, 256>>>(src, dst, E);

    k_gemm1   <<<(N + 255) / 256, 256>>>(x, W1, N);

    long long t1 = (long long)N * 8;
    k_gather1l2<<<(unsigned)((t1 + 255) / 256), 256>>>(W2, b1, N);

    long long t2 = (long long)N * 4;
    k_gather2 <<<(unsigned)((t2 + 255) / 256), 256>>>(out, b2, N);
}

// round 11
// speedup vs baseline: 1.9587x; 1.9587x over previous
#include <cuda_runtime.h>
#include <cuda_fp16.h>

#define NMAX   100000
#define EMAX   3200000
#define FIN    128
#define FH     64
#define FC     16
#define SCANB  1024
#define NBLK   ((NMAX + SCANB - 1) / SCANB)   // 98

// ---- scratch (allocation-free: __device__ globals) ----
__device__ __align__(16) __half g_h1h[NMAX * FH];   // layer-1 h' = (x@W1)*dinv, fp16
__device__ __align__(16) float  g_agg1[NMAX * FH];  // gathered layer-1 (incl. self), fp32
__device__ __align__(16) __half g_h2h[NMAX * FC];   // layer-2 h' = (z@W2)*dinv, fp16
__device__ int   g_deg[NMAX];
__device__ float g_dinv[NMAX];
__device__ int   g_rowstart[NMAX + 1];
__device__ int   g_cursor[NMAX];
__device__ int   g_adj[EMAX];                        // CSR by dst: stores src ids
__device__ int   g_bsum[NBLK];
__device__ int   g_boff[NBLK];

// ---------------------------------------------------------------------------
// f32x2 packed-FMA helpers (sm_100+; ptxas won't auto-fuse from C++)
__device__ __forceinline__ unsigned long long pack2(float a, float b) {
    unsigned long long r;
    asm("mov.b64 %0, {%1, %2};" : "=l"(r) : "f"(a), "f"(b));
    return r;
}
__device__ __forceinline__ void unpack2(unsigned long long v, float& a, float& b) {
    asm("mov.b64 {%0, %1}, %2;" : "=f"(a), "=f"(b) : "l"(v));
}
__device__ __forceinline__ void fma2(unsigned long long& d,
                                     unsigned long long a, unsigned long long b) {
    asm("fma.rn.f32x2 %0, %1, %2, %0;" : "+l"(d) : "l"(a), "l"(b));
}

// ---------------------------------------------------------------------------
__global__ void k_zero_deg(int n) {
    int i = blockIdx.x * blockDim.x + threadIdx.x;
    if (i < n) g_deg[i] = 0;
}

__global__ void k_degree(const int* __restrict__ dst, int e) {
    int i = blockIdx.x * blockDim.x + threadIdx.x;
    if (i < e) atomicAdd(&g_deg[dst[i]], 1);
}

// ---- prefix scan (exclusive) of g_deg -> g_rowstart, dinv fused ----
__global__ void k_scan1(int n) {
    __shared__ int s[SCANB];
    int i = blockIdx.x * SCANB + threadIdx.x;
    int v = (i < n) ? g_deg[i] : 0;
    if (i < n) g_dinv[i] = rsqrtf((float)v + 1.0f);
    s[threadIdx.x] = v;
    __syncthreads();
    for (int off = 1; off < SCANB; off <<= 1) {
        int t = (threadIdx.x >= off) ? s[threadIdx.x - off] : 0;
        __syncthreads();
        s[threadIdx.x] += t;
        __syncthreads();
    }
    if (i < n) g_rowstart[i] = s[threadIdx.x] - v;   // exclusive, block-local
    if (threadIdx.x == SCANB - 1) g_bsum[blockIdx.x] = s[SCANB - 1];
}

// parallel scan of block sums (one 128-thread block)
__global__ void k_scan2(int nb) {
    __shared__ int s[128];
    int tid = threadIdx.x;
    int v = (tid < nb) ? g_bsum[tid] : 0;
    s[tid] = v;
    __syncthreads();
    for (int off = 1; off < 128; off <<= 1) {
        int t = (tid >= off) ? s[tid - off] : 0;
        __syncthreads();
        s[tid] += t;
        __syncthreads();
    }
    if (tid < nb) g_boff[tid] = s[tid] - v;   // exclusive
}

__global__ void k_scan3(int n, int e) {
    int i = blockIdx.x * blockDim.x + threadIdx.x;
    if (i < n) {
        int r = g_rowstart[i] + g_boff[i / SCANB];
        g_rowstart[i] = r;
        g_cursor[i]   = r;
    }
    if (i == 0) g_rowstart[n] = e;
}

__global__ void k_fill(const int* __restrict__ src, const int* __restrict__ dst, int e) {
    int i = blockIdx.x * blockDim.x + threadIdx.x;
    if (i >= e) return;
    int pos = atomicAdd(&g_cursor[dst[i]], 1);
    g_adj[pos] = src[i];
}

// ---------------------------------------------------------------------------
// Layer-1 GEMM: h1[row] = (x[row] @ W1) * dinv[row], stored fp16.
// Register tile: 4 rows x 16 cols per thread, f32x2 packed FMA.
__global__ void __launch_bounds__(256) k_gemm1(const float* __restrict__ x,
                                               const float* __restrict__ W1, int n) {
    __shared__ float Ws[FIN * FH];   // 32 KB, [k][j]
    for (int i = threadIdx.x; i < (FIN * FH) / 4; i += blockDim.x)
        reinterpret_cast<float4*>(Ws)[i] = reinterpret_cast<const float4*>(W1)[i];
    __syncthreads();

    int c16  = threadIdx.x & 3;                 // which 16-col group
    int quad = threadIdx.x >> 2;                // 0..63
    int row0 = blockIdx.x * 256 + quad * 4;

    unsigned long long acc[4][8];
#pragma unroll
    for (int r = 0; r < 4; r++)
#pragma unroll
        for (int p = 0; p < 8; p++) acc[r][p] = 0ull;

    for (int k4 = 0; k4 < FIN / 4; k4++) {
        float4 xv[4];
#pragma unroll
        for (int r = 0; r < 4; r++) {
            int row = row0 + r;
            xv[r] = (row < n)
                ? reinterpret_cast<const float4*>(x + (size_t)row * FIN)[k4]
                : make_float4(0.f, 0.f, 0.f, 0.f);
        }
#pragma unroll
        for (int kk = 0; kk < 4; kk++) {
            int k = k4 * 4 + kk;
            const unsigned long long* wp =
                reinterpret_cast<const unsigned long long*>(Ws + k * FH + c16 * 16);
            unsigned long long w[8];
#pragma unroll
            for (int p = 0; p < 8; p++) w[p] = wp[p];
#pragma unroll
            for (int r = 0; r < 4; r++) {
                float xk = (kk == 0) ? xv[r].x : (kk == 1) ? xv[r].y
                         : (kk == 2) ? xv[r].z : xv[r].w;
                unsigned long long xk2 = pack2(xk, xk);
#pragma unroll
                for (int p = 0; p < 8; p++) fma2(acc[r][p], xk2, w[p]);
            }
        }
    }

#pragma unroll
    for (int r = 0; r < 4; r++) {
        int row = row0 + r;
        if (row >= n) continue;
        float dv = g_dinv[row];
        __align__(16) __half2 hv[8];
#pragma unroll
        for (int p = 0; p < 8; p++) {
            float a, b;
            unpack2(acc[r][p], a, b);
            hv[p] = __floats2half2_rn(a * dv, b * dv);
        }
        const uint4* wsrc = reinterpret_cast<const uint4*>(hv);
        uint4* o = reinterpret_cast<uint4*>(g_h1h + (size_t)row * FH + c16 * 16);
        o[0] = wsrc[0];
        o[1] = wsrc[1];
    }
}

// ---------------------------------------------------------------------------
// gather1: 8 threads per dst node; thread j accumulates halves [j*8, j*8+8)
// over all neighbors (CSR), fp32 accumulation, init = self (h1[d]).
// Lean on purpose: ~32 regs so occupancy hides the adj->h1 latency chain.
__device__ __forceinline__ void accum_h8(float* acc, uint4 v, bool init) {
    __align__(16) uint4 tmp = v;
    const __half2* h2p = reinterpret_cast<const __half2*>(&tmp);
#pragma unroll
    for (int q = 0; q < 4; q++) {
        float2 f = __half22float2(h2p[q]);
        if (init) { acc[q * 2] = f.x;  acc[q * 2 + 1] = f.y; }
        else      { acc[q * 2] += f.x; acc[q * 2 + 1] += f.y; }
    }
}

__global__ void k_gather1(int n) {
    long long t = (long long)blockIdx.x * blockDim.x + threadIdx.x;
    int j = (int)(t & 7);
    int d = (int)(t >> 3);
    if (d >= n) return;

    int rs = g_rowstart[d];
    int re = g_rowstart[d + 1];

    float acc[8];
    accum_h8(acc, reinterpret_cast<const uint4*>(g_h1h + (size_t)d * FH + j * 8)[0], true);

    for (int e = rs; e < re; e++) {
        int s = g_adj[e];
        accum_h8(acc, reinterpret_cast<const uint4*>(g_h1h + (size_t)s * FH + j * 8)[0], false);
    }

    float4* o = reinterpret_cast<float4*>(g_agg1 + (size_t)d * FH + j * 8);
    o[0] = make_float4(acc[0], acc[1], acc[2], acc[3]);
    o[1] = make_float4(acc[4], acc[5], acc[6], acc[7]);
}

// ---------------------------------------------------------------------------
// Fused layer-1 epilogue + layer-2 GEMM:
//   z = relu(dinv*agg1 + b1);  h2 = (z @ W2) * dinv   (stored fp16)
__global__ void k_layer2(const float* __restrict__ W2, const float* __restrict__ b1, int n) {
    __shared__ float Ws[FH * FC];
    __shared__ float b1s[FH];
    for (int i = threadIdx.x; i < (FH * FC) / 4; i += blockDim.x)
        reinterpret_cast<float4*>(Ws)[i] = reinterpret_cast<const float4*>(W2)[i];
    if (threadIdx.x < FH) b1s[threadIdx.x] = b1[threadIdx.x];
    __syncthreads();

    int row = blockIdx.x * blockDim.x + threadIdx.x;
    if (row >= n) return;

    float dv = g_dinv[row];

    float4 ar[FH / 4];
    const float4* a4 = reinterpret_cast<const float4*>(g_agg1 + (size_t)row * FH);
#pragma unroll
    for (int i = 0; i < FH / 4; i++) ar[i] = a4[i];

    float acc[FC];
#pragma unroll
    for (int j = 0; j < FC; j++) acc[j] = 0.0f;

#pragma unroll
    for (int k4 = 0; k4 < FH / 4; k4++) {
#pragma unroll
        for (int kk = 0; kk < 4; kk++) {
            int k = k4 * 4 + kk;
            float a = (kk == 0) ? ar[k4].x : (kk == 1) ? ar[k4].y
                    : (kk == 2) ? ar[k4].z : ar[k4].w;
            float z = fmaxf(fmaf(dv, a, b1s[k]), 0.0f);
#pragma unroll
            for (int j = 0; j < FC; j++) acc[j] = fmaf(z, Ws[k * FC + j], acc[j]);
        }
    }

    __align__(16) __half2 hv[FC / 2];
#pragma unroll
    for (int q = 0; q < FC / 2; q++)
        hv[q] = __floats2half2_rn(acc[q * 2] * dv, acc[q * 2 + 1] * dv);
    uint4* o = reinterpret_cast<uint4*>(g_h2h + (size_t)row * FC);
    o[0] = reinterpret_cast<const uint4*>(hv)[0];
    o[1] = reinterpret_cast<const uint4*>(hv)[1];
}

// ---------------------------------------------------------------------------
// gather2 (+ fused final): 4 threads per dst, fp16 h2;
//   out = dinv[d]*(h2[d] + sum h2[src]) + b2
__global__ void k_gather2(float* __restrict__ out, const float* __restrict__ b2, int n) {
    long long t = (long long)blockIdx.x * blockDim.x + threadIdx.x;
    int j = (int)(t & 3);
    int d = (int)(t >> 2);
    if (d >= n) return;

    int rs = g_rowstart[d];
    int re = g_rowstart[d + 1];

    float acc[4];
    {
        __align__(8) uint2 v = reinterpret_cast<const uint2*>(g_h2h + (size_t)d * FC + j * 4)[0];
        const __half2* h2p = reinterpret_cast<const __half2*>(&v);
        float2 f0 = __half22float2(h2p[0]);
        float2 f1 = __half22float2(h2p[1]);
        acc[0] = f0.x; acc[1] = f0.y; acc[2] = f1.x; acc[3] = f1.y;
    }
    for (int e = rs; e < re; e++) {
        int s = g_adj[e];
        __align__(8) uint2 v = reinterpret_cast<const uint2*>(g_h2h + (size_t)s * FC + j * 4)[0];
        const __half2* h2p = reinterpret_cast<const __half2*>(&v);
        float2 f0 = __half22float2(h2p[0]);
        float2 f1 = __half22float2(h2p[1]);
        acc[0] += f0.x; acc[1] += f0.y; acc[2] += f1.x; acc[3] += f1.y;
    }

    float dv = g_dinv[d];
    float4 bb = reinterpret_cast<const float4*>(b2)[j];
    float4 o;
    o.x = fmaf(dv, acc[0], bb.x);
    o.y = fmaf(dv, acc[1], bb.y);
    o.z = fmaf(dv, acc[2], bb.z);
    o.w = fmaf(dv, acc[3], bb.w);
    reinterpret_cast<float4*>(out + (size_t)d * FC + j * 4)[0] = o;
}

// ---------------------------------------------------------------------------
extern "C" void kernel_launch(void* const* d_in, const int* in_sizes, int n_in,
                              void* d_out, int out_size) {
    const float* x  = (const float*)d_in[0];
    const int*   ei = (const int*)d_in[1];   // int32 (JAX x64 disabled)
    const float* W1 = (const float*)d_in[2];
    const float* b1 = (const float*)d_in[3];
    const float* W2 = (const float*)d_in[4];
    const float* b2 = (const float*)d_in[5];
    float* out = (float*)d_out;

    int N = in_sizes[0] / FIN;
    int E = in_sizes[1] / 2;
    const int* src = ei;
    const int* dst = ei + E;
    int nb = (N + SCANB - 1) / SCANB;

    k_zero_deg<<<(N + 255) / 256, 256>>>(N);
    k_degree  <<<(E + 255) / 256, 256>>>(dst, E);

    k_scan1   <<<nb, SCANB>>>(N);
    k_scan2   <<<1, 128>>>(nb);
    k_scan3   <<<(N + 255) / 256, 256>>>(N, E);
    k_fill    <<<(E + 255) / 256, 256>>>(src, dst, E);

    k_gemm1   <<<(N + 255) / 256, 256>>>(x, W1, N);

    long long t1 = (long long)N * 8;
    k_gather1 <<<(unsigned)((t1 + 255) / 256), 256>>>(N);

    k_layer2  <<<(N + 255) / 256, 256>>>(W2, b1, N);

    long long t2 = (long long)N * 4;
    k_gather2 <<<(unsigned)((t2 + 255) / 256), 256>>>(out, b2, N);
}